// round 7
// baseline (speedup 1.0000x reference)
#include <cuda_runtime.h>
#include <cstdint>

#define NN 50000
#define NE 25000
#define CC 128
#define MAXINC 700000

// ---- scratch (device globals; no allocation) ----
__device__ __align__(16) float g_emean[NE * CC];  // per-edge mean of gathered x
__device__ __align__(16) float g_t[NE * CC];      // relu(mean @ W1^T + b1)
__device__ __align__(16) float g_e2[NE * CC];     // t @ W2^T + b2
__device__ __align__(16) float g_WT1[CC * CC];    // W1 transposed: [k][n]
__device__ __align__(16) float g_WT2[CC * CC];    // W2 transposed: [k][n]
// CSR structures
__device__ int g_cc_e[NE];        // per-edge degree
__device__ int g_cc_n[NN];        // per-node degree
__device__ int g_off_e[NE];       // exclusive scan (start offsets)
__device__ int g_off_n[NN];
__device__ int g_pos_e[NE];       // mutable cursor for fill
__device__ int g_pos_n[NN];
__device__ int g_lst_e[MAXINC];   // node ids grouped by edge
__device__ int g_lst_n[MAXINC];   // edge ids grouped by node

// ---- prep: zero degree counters + transpose weights ----
__global__ void prep_kernel(const float* __restrict__ W1,
                            const float* __restrict__ W2) {
    int tid = blockIdx.x * blockDim.x + threadIdx.x;
    int stride = gridDim.x * blockDim.x;
    for (int i = tid; i < NE; i += stride) g_cc_e[i] = 0;
    for (int i = tid; i < NN; i += stride) g_cc_n[i] = 0;
    for (int i = tid; i < CC * CC; i += stride) {
        int n = i >> 7;
        int k = i & 127;
        g_WT1[k * CC + n] = W1[i];
        g_WT2[k * CC + n] = W2[i];
    }
}

// ---- count incidences per edge and per node ----
__global__ void count_kernel(const int* __restrict__ nidx,
                             const int* __restrict__ eidx, int ninc) {
    int i = blockIdx.x * blockDim.x + threadIdx.x;
    if (i < ninc) {
        atomicAdd(&g_cc_e[__ldg(eidx + i)], 1);
        atomicAdd(&g_cc_n[__ldg(nidx + i)], 1);
    }
}

// ---- exclusive prefix scan; block 0 -> edges, block 1 -> nodes ----
__global__ void __launch_bounds__(1024) scan_kernel() {
    const int* cc = blockIdx.x ? g_cc_n : g_cc_e;
    int* off = blockIdx.x ? g_off_n : g_off_e;
    int* pos = blockIdx.x ? g_pos_n : g_pos_e;
    int n = blockIdx.x ? NN : NE;

    __shared__ int warp_sums[32];
    __shared__ int s_carry;
    int tid = threadIdx.x, lane = tid & 31, wid = tid >> 5;
    if (tid == 0) s_carry = 0;
    __syncthreads();

    for (int base = 0; base < n; base += 1024) {
        int i = base + tid;
        int v = (i < n) ? cc[i] : 0;
        int s = v;
#pragma unroll
        for (int d = 1; d < 32; d <<= 1) {
            int t = __shfl_up_sync(0xffffffffu, s, d);
            if (lane >= d) s += t;
        }
        if (lane == 31) warp_sums[wid] = s;
        __syncthreads();
        if (wid == 0) {
            int ws = warp_sums[lane];
#pragma unroll
            for (int d = 1; d < 32; d <<= 1) {
                int t = __shfl_up_sync(0xffffffffu, ws, d);
                if (lane >= d) ws += t;
            }
            warp_sums[lane] = ws;
        }
        __syncthreads();
        int carry = s_carry;
        int excl = s - v + (wid ? warp_sums[wid - 1] : 0) + carry;
        if (i < n) { off[i] = excl; pos[i] = excl; }
        int chunk_total = warp_sums[31];
        __syncthreads();
        if (tid == 0) s_carry = carry + chunk_total;
        __syncthreads();
    }
}

// ---- fill adjacency lists ----
__global__ void fill_kernel(const int* __restrict__ nidx,
                            const int* __restrict__ eidx, int ninc) {
    int i = blockIdx.x * blockDim.x + threadIdx.x;
    if (i < ninc) {
        int n = __ldg(nidx + i);
        int e = __ldg(eidx + i);
        int p = atomicAdd(&g_pos_e[e], 1);
        g_lst_e[p] = n;
        int q = atomicAdd(&g_pos_n[n], 1);
        g_lst_n[q] = e;
    }
}

// ---- gather1: g_emean[e] = mean of x[n] over incident nodes ----
__global__ void gather1_kernel(const float* __restrict__ x) {
    int gw = (blockIdx.x * blockDim.x + threadIdx.x) >> 5;
    int lane = threadIdx.x & 31;
    if (gw >= NE) return;
    int off = g_off_e[gw];
    int deg = g_cc_e[gw];
    float4 acc = make_float4(0.f, 0.f, 0.f, 0.f);
    int j = 0;
    for (; j + 4 <= deg; j += 4) {
        int n0 = __ldg(g_lst_e + off + j);
        int n1 = __ldg(g_lst_e + off + j + 1);
        int n2 = __ldg(g_lst_e + off + j + 2);
        int n3 = __ldg(g_lst_e + off + j + 3);
        float4 v0 = *reinterpret_cast<const float4*>(x + (size_t)n0 * CC + lane * 4);
        float4 v1 = *reinterpret_cast<const float4*>(x + (size_t)n1 * CC + lane * 4);
        float4 v2 = *reinterpret_cast<const float4*>(x + (size_t)n2 * CC + lane * 4);
        float4 v3 = *reinterpret_cast<const float4*>(x + (size_t)n3 * CC + lane * 4);
        acc.x += v0.x + v1.x + v2.x + v3.x;
        acc.y += v0.y + v1.y + v2.y + v3.y;
        acc.z += v0.z + v1.z + v2.z + v3.z;
        acc.w += v0.w + v1.w + v2.w + v3.w;
    }
    for (; j < deg; j++) {
        int n0 = __ldg(g_lst_e + off + j);
        float4 v0 = *reinterpret_cast<const float4*>(x + (size_t)n0 * CC + lane * 4);
        acc.x += v0.x; acc.y += v0.y; acc.z += v0.z; acc.w += v0.w;
    }
    float s = 1.f / (float)max(deg, 1);
    acc.x *= s; acc.y *= s; acc.z *= s; acc.w *= s;
    *reinterpret_cast<float4*>(g_emean + (size_t)gw * CC + lane * 4) = acc;
}

// ---- gather2: out[n] = relu(mean of g_e2[e] over incident edges) ----
__global__ void gather2_kernel(float* __restrict__ out) {
    int gw = (blockIdx.x * blockDim.x + threadIdx.x) >> 5;
    int lane = threadIdx.x & 31;
    if (gw >= NN) return;
    int off = g_off_n[gw];
    int deg = g_cc_n[gw];
    float4 acc = make_float4(0.f, 0.f, 0.f, 0.f);
    int j = 0;
    for (; j + 4 <= deg; j += 4) {
        int e0 = __ldg(g_lst_n + off + j);
        int e1 = __ldg(g_lst_n + off + j + 1);
        int e2i = __ldg(g_lst_n + off + j + 2);
        int e3 = __ldg(g_lst_n + off + j + 3);
        float4 v0 = *reinterpret_cast<const float4*>(g_e2 + (size_t)e0 * CC + lane * 4);
        float4 v1 = *reinterpret_cast<const float4*>(g_e2 + (size_t)e1 * CC + lane * 4);
        float4 v2 = *reinterpret_cast<const float4*>(g_e2 + (size_t)e2i * CC + lane * 4);
        float4 v3 = *reinterpret_cast<const float4*>(g_e2 + (size_t)e3 * CC + lane * 4);
        acc.x += v0.x + v1.x + v2.x + v3.x;
        acc.y += v0.y + v1.y + v2.y + v3.y;
        acc.z += v0.z + v1.z + v2.z + v3.z;
        acc.w += v0.w + v1.w + v2.w + v3.w;
    }
    for (; j < deg; j++) {
        int e0 = __ldg(g_lst_n + off + j);
        float4 v0 = *reinterpret_cast<const float4*>(g_e2 + (size_t)e0 * CC + lane * 4);
        acc.x += v0.x; acc.y += v0.y; acc.z += v0.z; acc.w += v0.w;
    }
    float s = 1.f / (float)max(deg, 1);
    acc.x = fmaxf(acc.x * s, 0.f);
    acc.y = fmaxf(acc.y * s, 0.f);
    acc.z = fmaxf(acc.z * s, 0.f);
    acc.w = fmaxf(acc.w * s, 0.f);
    *reinterpret_cast<float4*>(out + (size_t)gw * CC + lane * 4) = acc;
}

// ---- fused GEMM: out = [relu]( A @ W^T + bias ), 64x128 tile, 4x8 micro ----
// STAGE 0: A=g_emean, W=g_WT1, out=g_t, relu
// STAGE 1: A=g_t, W=g_WT2, out=g_e2, no relu
template <int STAGE>
__global__ void __launch_bounds__(256) gemm_kernel(const float* __restrict__ bias) {
    const float* __restrict__ A  = (STAGE == 0) ? g_emean : g_t;
    const float* __restrict__ WT = (STAGE == 0) ? g_WT1 : g_WT2;
    float* __restrict__ out      = (STAGE == 0) ? g_t : g_e2;
    constexpr bool RELU = (STAGE == 0);
    const int M = NE;
    constexpr int APAD = 68;

    __shared__ __align__(16) float As[32][APAD];   // [k][m]
    __shared__ __align__(16) float Bs[32][128];    // [k][n]

    const int tid = threadIdx.x;
    const int ty = tid >> 4;
    const int tx = tid & 15;
    const int row0 = blockIdx.x * 64;

    float acc[4][8];
#pragma unroll
    for (int i = 0; i < 4; i++)
#pragma unroll
        for (int j = 0; j < 8; j++) acc[i][j] = 0.f;

    float bias_r[8];
#pragma unroll
    for (int j = 0; j < 8; j++) bias_r[j] = __ldg(bias + tx * 8 + j);

    const int ar  = tid >> 3;
    const int akq = tid & 7;
    const int bk  = tid >> 3;
    const int bnq = tid & 7;

    float4 ra[2], rb[4];
    auto ldg_chunk = [&](int kb) {
#pragma unroll
        for (int p = 0; p < 2; p++) {
            int gm = row0 + ar + p * 32;
            float4 v = make_float4(0.f, 0.f, 0.f, 0.f);
            if (gm < M)
                v = *reinterpret_cast<const float4*>(A + (size_t)gm * CC + kb + akq * 4);
            ra[p] = v;
        }
#pragma unroll
        for (int p = 0; p < 4; p++) {
            int n4 = bnq + 8 * p;
            rb[p] = *reinterpret_cast<const float4*>(WT + (size_t)(kb + bk) * CC + n4 * 4);
        }
    };
    auto sts_chunk = [&]() {
#pragma unroll
        for (int p = 0; p < 2; p++) {
            int r = ar + p * 32;
            As[akq * 4 + 0][r] = ra[p].x;
            As[akq * 4 + 1][r] = ra[p].y;
            As[akq * 4 + 2][r] = ra[p].z;
            As[akq * 4 + 3][r] = ra[p].w;
        }
#pragma unroll
        for (int p = 0; p < 4; p++) {
            int n4 = bnq + 8 * p;
            *reinterpret_cast<float4*>(&Bs[bk][n4 * 4]) = rb[p];
        }
    };

    ldg_chunk(0);
    sts_chunk();
    __syncthreads();

#pragma unroll
    for (int c = 0; c < 4; c++) {
        if (c < 3) ldg_chunk((c + 1) * 32);
#pragma unroll
        for (int k = 0; k < 32; k++) {
            float4 av = *reinterpret_cast<float4*>(&As[k][ty * 4]);
            float4 b0 = *reinterpret_cast<float4*>(&Bs[k][tx * 8]);
            float4 b1 = *reinterpret_cast<float4*>(&Bs[k][tx * 8 + 4]);
            float a[4] = {av.x, av.y, av.z, av.w};
            float b[8] = {b0.x, b0.y, b0.z, b0.w, b1.x, b1.y, b1.z, b1.w};
#pragma unroll
            for (int i = 0; i < 4; i++)
#pragma unroll
                for (int j = 0; j < 8; j++) acc[i][j] += a[i] * b[j];
        }
        if (c < 3) {
            __syncthreads();
            sts_chunk();
            __syncthreads();
        }
    }

#pragma unroll
    for (int i = 0; i < 4; i++) {
        int gm = row0 + ty * 4 + i;
        if (gm < M) {
            float v0[4], v1[4];
#pragma unroll
            for (int j = 0; j < 4; j++) {
                float v = acc[i][j] + bias_r[j];
                v0[j] = RELU ? fmaxf(v, 0.f) : v;
            }
#pragma unroll
            for (int j = 0; j < 4; j++) {
                float v = acc[i][4 + j] + bias_r[4 + j];
                v1[j] = RELU ? fmaxf(v, 0.f) : v;
            }
            float4* o = reinterpret_cast<float4*>(out + (size_t)gm * CC + tx * 8);
            o[0] = make_float4(v0[0], v0[1], v0[2], v0[3]);
            o[1] = make_float4(v1[0], v1[1], v1[2], v1[3]);
        }
    }
}

extern "C" void kernel_launch(void* const* d_in, const int* in_sizes, int n_in,
                              void* d_out, int out_size) {
    const float* x  = (const float*)d_in[0];
    const int*   hi = (const int*)d_in[1];
    const float* W1 = (const float*)d_in[2];
    const float* b1 = (const float*)d_in[3];
    const float* W2 = (const float*)d_in[4];
    const float* b2 = (const float*)d_in[5];
    float* out = (float*)d_out;

    int ninc = in_sizes[1] / 2;
    const int* nidx = hi;          // hyperedge_index[0]
    const int* eidx = hi + ninc;   // hyperedge_index[1]

    prep_kernel<<<512, 256>>>(W1, W2);
    count_kernel<<<(ninc + 255) / 256, 256>>>(nidx, eidx, ninc);
    scan_kernel<<<2, 1024>>>();
    fill_kernel<<<(ninc + 255) / 256, 256>>>(nidx, eidx, ninc);
    gather1_kernel<<<(NE * 32 + 255) / 256, 256>>>(x);
    gemm_kernel<0><<<(NE + 63) / 64, 256>>>(b1);
    gemm_kernel<1><<<(NE + 63) / 64, 256>>>(b2);
    gather2_kernel<<<(NN * 32 + 255) / 256, 256>>>(out);
}

// round 8
// speedup vs baseline: 1.4971x; 1.4971x over previous
#include <cuda_runtime.h>
#include <cstdint>

#define NN 50000
#define NE 25000
#define CC 128

// ---- scratch (device globals; no allocation) ----
__device__ __align__(16) float g_esum[NE * CC];   // per-edge sum of gathered x
__device__ __align__(16) float g_t[NE * CC];      // relu(mean @ W1^T + b1)
__device__ __align__(16) float g_e2[NE * CC];     // t @ W2^T + b2
__device__ __align__(16) float g_cnt_e[NE];
__device__ __align__(16) float g_cnt_n[NN];

// ---- zero accumulators (incl. d_out, which is poisoned) ----
__global__ void prep_kernel(float* __restrict__ out) {
    int tid = blockIdx.x * blockDim.x + threadIdx.x;
    int stride = gridDim.x * blockDim.x;
    float4 z = make_float4(0.f, 0.f, 0.f, 0.f);
    float4* p1 = reinterpret_cast<float4*>(g_esum);
    for (int i = tid; i < NE * CC / 4; i += stride) p1[i] = z;
    float4* p2 = reinterpret_cast<float4*>(out);
    for (int i = tid; i < NN * CC / 4; i += stride) p2[i] = z;
    float4* p3 = reinterpret_cast<float4*>(g_cnt_e);
    for (int i = tid; i < NE / 4; i += stride) p3[i] = z;
    float4* p4 = reinterpret_cast<float4*>(g_cnt_n);
    for (int i = tid; i < NN / 4; i += stride) p4[i] = z;
}

// ---- scatter1: x[node] -> esum[edge] via vector reductions; counts too ----
__global__ void scatter1_kernel(const float* __restrict__ x,
                                const int* __restrict__ nidx,
                                const int* __restrict__ eidx, int ninc) {
    int gw = (blockIdx.x * blockDim.x + threadIdx.x) >> 5;
    int lane = threadIdx.x & 31;
    if (gw >= ninc) return;
    int n = __ldg(nidx + gw);
    int e = __ldg(eidx + gw);
    float4 v = *reinterpret_cast<const float4*>(x + (size_t)n * CC + lane * 4);
    float* dst = g_esum + (size_t)e * CC + lane * 4;
    asm volatile("red.global.add.v4.f32 [%0], {%1,%2,%3,%4};"
                 :: "l"(dst), "f"(v.x), "f"(v.y), "f"(v.z), "f"(v.w)
                 : "memory");
    if (lane == 0) {
        atomicAdd(g_cnt_e + e, 1.0f);
        atomicAdd(g_cnt_n + n, 1.0f);
    }
}

// ---- scatter2: e2[edge] -> out[node] ----
__global__ void scatter2_kernel(const int* __restrict__ nidx,
                                const int* __restrict__ eidx,
                                float* __restrict__ out, int ninc) {
    int gw = (blockIdx.x * blockDim.x + threadIdx.x) >> 5;
    int lane = threadIdx.x & 31;
    if (gw >= ninc) return;
    int n = __ldg(nidx + gw);
    int e = __ldg(eidx + gw);
    float4 v = *reinterpret_cast<const float4*>(g_e2 + (size_t)e * CC + lane * 4);
    float* dst = out + (size_t)n * CC + lane * 4;
    asm volatile("red.global.add.v4.f32 [%0], {%1,%2,%3,%4};"
                 :: "l"(dst), "f"(v.x), "f"(v.y), "f"(v.z), "f"(v.w)
                 : "memory");
}

__device__ __forceinline__ uint32_t f2tf32(float f) {
    uint32_t u;
    asm("cvt.rna.tf32.f32 %0, %1;" : "=r"(u) : "f"(f));
    return u;
}

// ---- tf32 tensor-core GEMM: out = [relu]( [A/cnt] @ W^T + bias ) ----
// Tile 64(M) x 128(N), BK=32, 256 threads = 8 warps (2 m x 4 n), warp: 32x32.
// A: [M][128] fp32; W: [N][K]=[128][128] native layout (B operand, col-major k).
// STAGE 0: A=g_esum scaled by 1/cnt_e, out=g_t, relu. STAGE 1: A=g_t, out=g_e2.
template <int STAGE>
__global__ void __launch_bounds__(256) gemm_tc(const float* __restrict__ W,
                                               const float* __restrict__ bias) {
    const float* __restrict__ A = (STAGE == 0) ? g_esum : g_t;
    float* __restrict__ out     = (STAGE == 0) ? g_t : g_e2;
    constexpr bool MEAN = (STAGE == 0);
    constexpr bool RELU = (STAGE == 0);
    const int M = NE;
    constexpr int LDS_K = 36;   // 32 + pad 4: (4g+tig) mod 32 all-distinct

    __shared__ uint32_t As[64][LDS_K];    // [m][k] tf32
    __shared__ uint32_t Bs[128][LDS_K];   // [n][k] tf32

    const int tid = threadIdx.x;
    const int lane = tid & 31;
    const int g = lane >> 2;     // 0..7
    const int tig = lane & 3;    // 0..3
    const int w = tid >> 5;      // 0..7
    const int wm = w >> 2;       // 0..1 -> 32 rows
    const int wn = w & 3;        // 0..3 -> 32 cols
    const int row0 = blockIdx.x * 64;

    float c[2][4][4];
#pragma unroll
    for (int mt = 0; mt < 2; mt++)
#pragma unroll
        for (int nt = 0; nt < 4; nt++)
#pragma unroll
            for (int r = 0; r < 4; r++) c[mt][nt][r] = 0.f;

    // loaders: A chunk 64x32 = 512 float4 (2/thread), B chunk 128x32 = 1024 float4 (4/thread)
    const int a_row = tid >> 3;       // 0..31 (+32)
    const int a_c4  = tid & 7;
    float ascale[2] = {1.f, 1.f};
    if (MEAN) {
#pragma unroll
        for (int p = 0; p < 2; p++) {
            int gm = row0 + a_row + p * 32;
            if (gm < M) ascale[p] = 1.f / fmaxf(__ldg(g_cnt_e + gm), 1.f);
        }
    }
    const int b_row = tid >> 1;       // 0..127
    const int b_c4  = (tid & 1) * 4;  // float4 cols 0..3 / 4..7

    float4 ra[2], rb[4];
    auto ldg_chunk = [&](int kb) {
#pragma unroll
        for (int p = 0; p < 2; p++) {
            int gm = row0 + a_row + p * 32;
            float4 v = make_float4(0.f, 0.f, 0.f, 0.f);
            if (gm < M)
                v = *reinterpret_cast<const float4*>(A + (size_t)gm * CC + kb + a_c4 * 4);
            if (MEAN) { v.x *= ascale[p]; v.y *= ascale[p]; v.z *= ascale[p]; v.w *= ascale[p]; }
            ra[p] = v;
        }
#pragma unroll
        for (int p = 0; p < 4; p++)
            rb[p] = *reinterpret_cast<const float4*>(
                W + (size_t)b_row * CC + kb + (b_c4 + p) * 4);
    };
    auto sts_chunk = [&]() {
#pragma unroll
        for (int p = 0; p < 2; p++) {
            int r = a_row + p * 32;
            As[r][a_c4 * 4 + 0] = f2tf32(ra[p].x);
            As[r][a_c4 * 4 + 1] = f2tf32(ra[p].y);
            As[r][a_c4 * 4 + 2] = f2tf32(ra[p].z);
            As[r][a_c4 * 4 + 3] = f2tf32(ra[p].w);
        }
#pragma unroll
        for (int p = 0; p < 4; p++) {
            int kcol = (b_c4 + p) * 4;
            Bs[b_row][kcol + 0] = f2tf32(rb[p].x);
            Bs[b_row][kcol + 1] = f2tf32(rb[p].y);
            Bs[b_row][kcol + 2] = f2tf32(rb[p].z);
            Bs[b_row][kcol + 3] = f2tf32(rb[p].w);
        }
    };

    ldg_chunk(0);
    sts_chunk();
    __syncthreads();

#pragma unroll
    for (int ch = 0; ch < 4; ch++) {
        if (ch < 3) ldg_chunk((ch + 1) * 32);
#pragma unroll
        for (int ks = 0; ks < 4; ks++) {
            const int k0 = ks * 8;
            uint32_t a[2][4];
#pragma unroll
            for (int mt = 0; mt < 2; mt++) {
                int mb = wm * 32 + mt * 16;
                a[mt][0] = As[mb + g][k0 + tig];
                a[mt][1] = As[mb + g + 8][k0 + tig];
                a[mt][2] = As[mb + g][k0 + tig + 4];
                a[mt][3] = As[mb + g + 8][k0 + tig + 4];
            }
            uint32_t b[4][2];
#pragma unroll
            for (int nt = 0; nt < 4; nt++) {
                int nb = wn * 32 + nt * 8;
                b[nt][0] = Bs[nb + g][k0 + tig];
                b[nt][1] = Bs[nb + g][k0 + tig + 4];
            }
#pragma unroll
            for (int mt = 0; mt < 2; mt++)
#pragma unroll
                for (int nt = 0; nt < 4; nt++) {
                    asm volatile(
                        "mma.sync.aligned.m16n8k8.row.col.f32.tf32.tf32.f32 "
                        "{%0,%1,%2,%3}, {%4,%5,%6,%7}, {%8,%9}, {%0,%1,%2,%3};"
                        : "+f"(c[mt][nt][0]), "+f"(c[mt][nt][1]),
                          "+f"(c[mt][nt][2]), "+f"(c[mt][nt][3])
                        : "r"(a[mt][0]), "r"(a[mt][1]), "r"(a[mt][2]), "r"(a[mt][3]),
                          "r"(b[nt][0]), "r"(b[nt][1]));
                }
        }
        if (ch < 3) {
            __syncthreads();
            sts_chunk();
            __syncthreads();
        }
    }

    // ---- epilogue: c layout: c0:(g, 2tig) c1:(g, 2tig+1) c2:(g+8, 2tig) c3:(g+8, 2tig+1)
#pragma unroll
    for (int nt = 0; nt < 4; nt++) {
        int col = wn * 32 + nt * 8 + tig * 2;
        float b0 = __ldg(bias + col);
        float b1 = __ldg(bias + col + 1);
#pragma unroll
        for (int mt = 0; mt < 2; mt++) {
            int mb = row0 + wm * 32 + mt * 16;
            int r0 = mb + g;
            int r1 = mb + g + 8;
            float v00 = c[mt][nt][0] + b0, v01 = c[mt][nt][1] + b1;
            float v10 = c[mt][nt][2] + b0, v11 = c[mt][nt][3] + b1;
            if (RELU) {
                v00 = fmaxf(v00, 0.f); v01 = fmaxf(v01, 0.f);
                v10 = fmaxf(v10, 0.f); v11 = fmaxf(v11, 0.f);
            }
            if (r0 < M)
                *reinterpret_cast<float2*>(out + (size_t)r0 * CC + col) = make_float2(v00, v01);
            if (r1 < M)
                *reinterpret_cast<float2*>(out + (size_t)r1 * CC + col) = make_float2(v10, v11);
        }
    }
}

// ---- finalize: out = relu(out / max(cnt_n, 1)) ----
__global__ void finalize_kernel(float* __restrict__ out) {
    int i = blockIdx.x * blockDim.x + threadIdx.x;
    int stride = gridDim.x * blockDim.x;
    float4* p = reinterpret_cast<float4*>(out);
    for (; i < NN * CC / 4; i += stride) {
        int m = i >> 5;  // 32 float4 per row
        float s = 1.f / fmaxf(g_cnt_n[m], 1.f);
        float4 v = p[i];
        v.x = fmaxf(v.x * s, 0.f);
        v.y = fmaxf(v.y * s, 0.f);
        v.z = fmaxf(v.z * s, 0.f);
        v.w = fmaxf(v.w * s, 0.f);
        p[i] = v;
    }
}

extern "C" void kernel_launch(void* const* d_in, const int* in_sizes, int n_in,
                              void* d_out, int out_size) {
    const float* x  = (const float*)d_in[0];
    const int*   hi = (const int*)d_in[1];
    const float* W1 = (const float*)d_in[2];
    const float* b1 = (const float*)d_in[3];
    const float* W2 = (const float*)d_in[4];
    const float* b2 = (const float*)d_in[5];
    float* out = (float*)d_out;

    int ninc = in_sizes[1] / 2;
    const int* nidx = hi;          // hyperedge_index[0]
    const int* eidx = hi + ninc;   // hyperedge_index[1]

    prep_kernel<<<1024, 256>>>(out);
    scatter1_kernel<<<(ninc + 7) / 8, 256>>>(x, nidx, eidx, ninc);
    gemm_tc<0><<<(NE + 63) / 64, 256>>>(W1, b1);
    gemm_tc<1><<<(NE + 63) / 64, 256>>>(W2, b2);
    scatter2_kernel<<<(ninc + 7) / 8, 256>>>(nidx, eidx, out, ninc);
    finalize_kernel<<<1024, 256>>>(out);
}

// round 9
// speedup vs baseline: 1.5668x; 1.0466x over previous
#include <cuda_runtime.h>
#include <cstdint>

#define NN 50000
#define NE 25000
#define CC 128

// ---- scratch (device globals; no allocation) ----
__device__ __align__(16) float g_esum[NE * CC];   // per-edge sum of gathered x
__device__ __align__(16) float g_e2[NE * CC];     // (relu(mean@W1^T+b1))@W2^T + b2
__device__ __align__(16) float g_cnt_e[NE];
__device__ __align__(16) float g_cnt_n[NN];

// ---- zero accumulators (incl. d_out, which is poisoned) ----
__global__ void prep_kernel(float* __restrict__ out) {
    int tid = blockIdx.x * blockDim.x + threadIdx.x;
    int stride = gridDim.x * blockDim.x;
    float4 z = make_float4(0.f, 0.f, 0.f, 0.f);
    float4* p1 = reinterpret_cast<float4*>(g_esum);
    for (int i = tid; i < NE * CC / 4; i += stride) p1[i] = z;
    float4* p2 = reinterpret_cast<float4*>(out);
    for (int i = tid; i < NN * CC / 4; i += stride) p2[i] = z;
    float4* p3 = reinterpret_cast<float4*>(g_cnt_e);
    for (int i = tid; i < NE / 4; i += stride) p3[i] = z;
    float4* p4 = reinterpret_cast<float4*>(g_cnt_n);
    for (int i = tid; i < NN / 4; i += stride) p4[i] = z;
}

// ---- scatter1: x[node] -> esum[edge] via vector reductions; counts too ----
__global__ void scatter1_kernel(const float* __restrict__ x,
                                const int* __restrict__ nidx,
                                const int* __restrict__ eidx, int ninc) {
    int gw = (blockIdx.x * blockDim.x + threadIdx.x) >> 5;
    int lane = threadIdx.x & 31;
    if (gw >= ninc) return;
    int n = __ldg(nidx + gw);
    int e = __ldg(eidx + gw);
    float4 v = *reinterpret_cast<const float4*>(x + (size_t)n * CC + lane * 4);
    float* dst = g_esum + (size_t)e * CC + lane * 4;
    asm volatile("red.global.add.v4.f32 [%0], {%1,%2,%3,%4};"
                 :: "l"(dst), "f"(v.x), "f"(v.y), "f"(v.z), "f"(v.w)
                 : "memory");
    if (lane == 0) {
        atomicAdd(g_cnt_e + e, 1.0f);
        atomicAdd(g_cnt_n + n, 1.0f);
    }
}

// ---- scatter2: e2[edge] -> out[node] ----
__global__ void scatter2_kernel(const int* __restrict__ nidx,
                                const int* __restrict__ eidx,
                                float* __restrict__ out, int ninc) {
    int gw = (blockIdx.x * blockDim.x + threadIdx.x) >> 5;
    int lane = threadIdx.x & 31;
    if (gw >= ninc) return;
    int n = __ldg(nidx + gw);
    int e = __ldg(eidx + gw);
    float4 v = *reinterpret_cast<const float4*>(g_e2 + (size_t)e * CC + lane * 4);
    float* dst = out + (size_t)n * CC + lane * 4;
    asm volatile("red.global.add.v4.f32 [%0], {%1,%2,%3,%4};"
                 :: "l"(dst), "f"(v.x), "f"(v.y), "f"(v.z), "f"(v.w)
                 : "memory");
}

__device__ __forceinline__ uint32_t f2tf32(float f) {
    uint32_t u;
    asm("cvt.rna.tf32.f32 %0, %1;" : "=r"(u) : "f"(f));
    return u;
}

// ---- fused double tf32 GEMM per 64-row tile ----
// Stage A: T = relu( (esum/cnt) @ W1^T + b1 )   [64 x 128], kept in smem (tf32)
// Stage B: e2 = T @ W2^T + b2                   [64 x 128], written to gmem
// 256 threads = 8 warps (2m x 4n), warp computes 32x32 via m16n8k8 tf32 MMA.
__global__ void __launch_bounds__(256) fused_gemm(const float* __restrict__ W1,
                                                  const float* __restrict__ b1,
                                                  const float* __restrict__ W2,
                                                  const float* __restrict__ b2) {
    extern __shared__ uint32_t smem[];
    uint32_t (*Ts)[132] = reinterpret_cast<uint32_t(*)[132]>(smem);            // 64x132
    uint32_t (*Bs)[36]  = reinterpret_cast<uint32_t(*)[36]>(smem + 64 * 132);  // 128x36
    uint32_t (*As)[36]  = reinterpret_cast<uint32_t(*)[36]>(smem + 64 * 132 + 128 * 36); // 64x36

    const int M = NE;
    const int tid = threadIdx.x;
    const int lane = tid & 31;
    const int g = lane >> 2;     // 0..7
    const int tig = lane & 3;    // 0..3
    const int w = tid >> 5;
    const int wm = w >> 2;       // 0..1
    const int wn = w & 3;        // 0..3
    const int row0 = blockIdx.x * 64;

    // loader mappings
    const int a_row = tid >> 3;       // 0..31 (+32)
    const int a_c4  = tid & 7;        // float4 col within 32-wide chunk
    const int b_row = tid >> 1;       // 0..127
    const int b_c4  = (tid & 1) * 4;  // float4 cols 0..3 / 4..7

    float ascale[2] = {1.f, 1.f};
#pragma unroll
    for (int p = 0; p < 2; p++) {
        int gm = row0 + a_row + p * 32;
        if (gm < M) ascale[p] = 1.f / fmaxf(__ldg(g_cnt_e + gm), 1.f);
    }

    float c[2][4][4];
#pragma unroll
    for (int mt = 0; mt < 2; mt++)
#pragma unroll
        for (int nt = 0; nt < 4; nt++)
#pragma unroll
            for (int r = 0; r < 4; r++) c[mt][nt][r] = 0.f;

    // ================= Stage A: T = relu(mean @ W1^T + b1) =================
#pragma unroll
    for (int ch = 0; ch < 4; ch++) {
        const int kb = ch * 32;
        float4 ra[2], rb[4];
#pragma unroll
        for (int p = 0; p < 2; p++) {
            int gm = row0 + a_row + p * 32;
            float4 v = make_float4(0.f, 0.f, 0.f, 0.f);
            if (gm < M)
                v = *reinterpret_cast<const float4*>(g_esum + (size_t)gm * CC + kb + a_c4 * 4);
            v.x *= ascale[p]; v.y *= ascale[p]; v.z *= ascale[p]; v.w *= ascale[p];
            ra[p] = v;
        }
#pragma unroll
        for (int p = 0; p < 4; p++)
            rb[p] = *reinterpret_cast<const float4*>(W1 + (size_t)b_row * CC + kb + (b_c4 + p) * 4);
        if (ch > 0) __syncthreads();
#pragma unroll
        for (int p = 0; p < 2; p++) {
            int r = a_row + p * 32;
            As[r][a_c4 * 4 + 0] = f2tf32(ra[p].x);
            As[r][a_c4 * 4 + 1] = f2tf32(ra[p].y);
            As[r][a_c4 * 4 + 2] = f2tf32(ra[p].z);
            As[r][a_c4 * 4 + 3] = f2tf32(ra[p].w);
        }
#pragma unroll
        for (int p = 0; p < 4; p++) {
            int kcol = (b_c4 + p) * 4;
            Bs[b_row][kcol + 0] = f2tf32(rb[p].x);
            Bs[b_row][kcol + 1] = f2tf32(rb[p].y);
            Bs[b_row][kcol + 2] = f2tf32(rb[p].z);
            Bs[b_row][kcol + 3] = f2tf32(rb[p].w);
        }
        __syncthreads();
#pragma unroll
        for (int ks = 0; ks < 4; ks++) {
            const int k0 = ks * 8;
            uint32_t a[2][4], b[4][2];
#pragma unroll
            for (int mt = 0; mt < 2; mt++) {
                int mb = wm * 32 + mt * 16;
                a[mt][0] = As[mb + g][k0 + tig];
                a[mt][1] = As[mb + g + 8][k0 + tig];
                a[mt][2] = As[mb + g][k0 + tig + 4];
                a[mt][3] = As[mb + g + 8][k0 + tig + 4];
            }
#pragma unroll
            for (int nt = 0; nt < 4; nt++) {
                int nb = wn * 32 + nt * 8;
                b[nt][0] = Bs[nb + g][k0 + tig];
                b[nt][1] = Bs[nb + g][k0 + tig + 4];
            }
#pragma unroll
            for (int mt = 0; mt < 2; mt++)
#pragma unroll
                for (int nt = 0; nt < 4; nt++)
                    asm volatile(
                        "mma.sync.aligned.m16n8k8.row.col.f32.tf32.tf32.f32 "
                        "{%0,%1,%2,%3}, {%4,%5,%6,%7}, {%8,%9}, {%0,%1,%2,%3};"
                        : "+f"(c[mt][nt][0]), "+f"(c[mt][nt][1]),
                          "+f"(c[mt][nt][2]), "+f"(c[mt][nt][3])
                        : "r"(a[mt][0]), "r"(a[mt][1]), "r"(a[mt][2]), "r"(a[mt][3]),
                          "r"(b[nt][0]), "r"(b[nt][1]));
        }
    }
    __syncthreads();

    // ---- write T = relu(c + b1) into Ts (tf32), reset accumulators ----
#pragma unroll
    for (int nt = 0; nt < 4; nt++) {
        int col = wn * 32 + nt * 8 + tig * 2;
        float bb0 = __ldg(b1 + col);
        float bb1 = __ldg(b1 + col + 1);
#pragma unroll
        for (int mt = 0; mt < 2; mt++) {
            int mb = wm * 32 + mt * 16;
            Ts[mb + g][col]         = f2tf32(fmaxf(c[mt][nt][0] + bb0, 0.f));
            Ts[mb + g][col + 1]     = f2tf32(fmaxf(c[mt][nt][1] + bb1, 0.f));
            Ts[mb + g + 8][col]     = f2tf32(fmaxf(c[mt][nt][2] + bb0, 0.f));
            Ts[mb + g + 8][col + 1] = f2tf32(fmaxf(c[mt][nt][3] + bb1, 0.f));
            c[mt][nt][0] = 0.f; c[mt][nt][1] = 0.f;
            c[mt][nt][2] = 0.f; c[mt][nt][3] = 0.f;
        }
    }

    // ================= Stage B: e2 = T @ W2^T + b2 =================
#pragma unroll
    for (int ch = 0; ch < 4; ch++) {
        const int kb = ch * 32;
        float4 rb[4];
#pragma unroll
        for (int p = 0; p < 4; p++)
            rb[p] = *reinterpret_cast<const float4*>(W2 + (size_t)b_row * CC + kb + (b_c4 + p) * 4);
        __syncthreads();   // prior mma (or Ts writes) done before Bs overwrite
#pragma unroll
        for (int p = 0; p < 4; p++) {
            int kcol = (b_c4 + p) * 4;
            Bs[b_row][kcol + 0] = f2tf32(rb[p].x);
            Bs[b_row][kcol + 1] = f2tf32(rb[p].y);
            Bs[b_row][kcol + 2] = f2tf32(rb[p].z);
            Bs[b_row][kcol + 3] = f2tf32(rb[p].w);
        }
        __syncthreads();
#pragma unroll
        for (int ks = 0; ks < 4; ks++) {
            const int k0 = ks * 8;
            const int kk = kb + k0;
            uint32_t a[2][4], b[4][2];
#pragma unroll
            for (int mt = 0; mt < 2; mt++) {
                int mb = wm * 32 + mt * 16;
                a[mt][0] = Ts[mb + g][kk + tig];
                a[mt][1] = Ts[mb + g + 8][kk + tig];
                a[mt][2] = Ts[mb + g][kk + tig + 4];
                a[mt][3] = Ts[mb + g + 8][kk + tig + 4];
            }
#pragma unroll
            for (int nt = 0; nt < 4; nt++) {
                int nb = wn * 32 + nt * 8;
                b[nt][0] = Bs[nb + g][k0 + tig];
                b[nt][1] = Bs[nb + g][k0 + tig + 4];
            }
#pragma unroll
            for (int mt = 0; mt < 2; mt++)
#pragma unroll
                for (int nt = 0; nt < 4; nt++)
                    asm volatile(
                        "mma.sync.aligned.m16n8k8.row.col.f32.tf32.tf32.f32 "
                        "{%0,%1,%2,%3}, {%4,%5,%6,%7}, {%8,%9}, {%0,%1,%2,%3};"
                        : "+f"(c[mt][nt][0]), "+f"(c[mt][nt][1]),
                          "+f"(c[mt][nt][2]), "+f"(c[mt][nt][3])
                        : "r"(a[mt][0]), "r"(a[mt][1]), "r"(a[mt][2]), "r"(a[mt][3]),
                          "r"(b[nt][0]), "r"(b[nt][1]));
        }
    }

    // ---- epilogue: e2 = c + b2 ----
#pragma unroll
    for (int nt = 0; nt < 4; nt++) {
        int col = wn * 32 + nt * 8 + tig * 2;
        float bb0 = __ldg(b2 + col);
        float bb1 = __ldg(b2 + col + 1);
#pragma unroll
        for (int mt = 0; mt < 2; mt++) {
            int mb = row0 + wm * 32 + mt * 16;
            int r0 = mb + g;
            int r1 = mb + g + 8;
            if (r0 < M)
                *reinterpret_cast<float2*>(g_e2 + (size_t)r0 * CC + col) =
                    make_float2(c[mt][nt][0] + bb0, c[mt][nt][1] + bb1);
            if (r1 < M)
                *reinterpret_cast<float2*>(g_e2 + (size_t)r1 * CC + col) =
                    make_float2(c[mt][nt][2] + bb0, c[mt][nt][3] + bb1);
        }
    }
}

// ---- finalize: out = relu(out / max(cnt_n, 1)) ----
__global__ void finalize_kernel(float* __restrict__ out) {
    int i = blockIdx.x * blockDim.x + threadIdx.x;
    int stride = gridDim.x * blockDim.x;
    float4* p = reinterpret_cast<float4*>(out);
    for (; i < NN * CC / 4; i += stride) {
        int m = i >> 5;
        float s = 1.f / fmaxf(g_cnt_n[m], 1.f);
        float4 v = p[i];
        v.x = fmaxf(v.x * s, 0.f);
        v.y = fmaxf(v.y * s, 0.f);
        v.z = fmaxf(v.z * s, 0.f);
        v.w = fmaxf(v.w * s, 0.f);
        p[i] = v;
    }
}

extern "C" void kernel_launch(void* const* d_in, const int* in_sizes, int n_in,
                              void* d_out, int out_size) {
    const float* x  = (const float*)d_in[0];
    const int*   hi = (const int*)d_in[1];
    const float* W1 = (const float*)d_in[2];
    const float* b1 = (const float*)d_in[3];
    const float* W2 = (const float*)d_in[4];
    const float* b2 = (const float*)d_in[5];
    float* out = (float*)d_out;

    int ninc = in_sizes[1] / 2;
    const int* nidx = hi;          // hyperedge_index[0]
    const int* eidx = hi + ninc;   // hyperedge_index[1]

    constexpr int SMEM_BYTES = (64 * 132 + 128 * 36 + 64 * 36) * 4;  // 61440
    static int attr_set = 0;
    if (!attr_set) {
        cudaFuncSetAttribute(fused_gemm, cudaFuncAttributeMaxDynamicSharedMemorySize,
                             SMEM_BYTES);
        attr_set = 1;
    }

    prep_kernel<<<1024, 256>>>(out);
    scatter1_kernel<<<(ninc + 7) / 8, 256>>>(x, nidx, eidx, ninc);
    fused_gemm<<<(NE + 63) / 64, 256, SMEM_BYTES>>>(W1, b1, W2, b2);
    scatter2_kernel<<<(ninc + 7) / 8, 256>>>(nidx, eidx, out, ninc);
    finalize_kernel<<<1024, 256>>>(out);
}

// round 10
// speedup vs baseline: 1.7609x; 1.1239x over previous
#include <cuda_runtime.h>
#include <cstdint>

#define NN 50000
#define NE 25000
#define CC 128

// ---- scratch (device globals; no allocation) ----
__device__ __align__(16) float g_esum[NE * CC];   // per-edge sum of gathered x
__device__ __align__(16) float g_e2[NE * CC];     // (relu(mean@W1^T+b1))@W2^T + b2
__device__ __align__(16) float g_cnt_e[NE];
__device__ __align__(16) float g_cnt_n[NN];

// ---- zero accumulators (incl. d_out, which is poisoned) ----
__global__ void prep_kernel(float* __restrict__ out) {
    int tid = blockIdx.x * blockDim.x + threadIdx.x;
    int stride = gridDim.x * blockDim.x;
    float4 z = make_float4(0.f, 0.f, 0.f, 0.f);
    float4* p1 = reinterpret_cast<float4*>(g_esum);
    for (int i = tid; i < NE * CC / 4; i += stride) p1[i] = z;
    float4* p2 = reinterpret_cast<float4*>(out);
    for (int i = tid; i < NN * CC / 4; i += stride) p2[i] = z;
    float4* p3 = reinterpret_cast<float4*>(g_cnt_e);
    for (int i = tid; i < NE / 4; i += stride) p3[i] = z;
    float4* p4 = reinterpret_cast<float4*>(g_cnt_n);
    for (int i = tid; i < NN / 4; i += stride) p4[i] = z;
}

// ---- scatter1: x[node] -> esum[edge], 4 incidences per warp for MLP ----
__global__ void scatter1_kernel(const float* __restrict__ x,
                                const int* __restrict__ nidx,
                                const int* __restrict__ eidx, int ninc) {
    int gw = (blockIdx.x * blockDim.x + threadIdx.x) >> 5;
    int lane = threadIdx.x & 31;
    int base = gw * 4;
    if (base >= ninc) return;
    int cnt = min(4, ninc - base);

    int n[4], e[4];
#pragma unroll
    for (int q = 0; q < 4; q++) {
        int i = (q < cnt) ? base + q : base;
        n[q] = __ldg(nidx + i);
        e[q] = __ldg(eidx + i);
    }
    float4 v[4];
#pragma unroll
    for (int q = 0; q < 4; q++)
        v[q] = *reinterpret_cast<const float4*>(x + (size_t)n[q] * CC + lane * 4);
#pragma unroll
    for (int q = 0; q < 4; q++) {
        if (q < cnt) {
            float* dst = g_esum + (size_t)e[q] * CC + lane * 4;
            asm volatile("red.global.add.v4.f32 [%0], {%1,%2,%3,%4};"
                         :: "l"(dst), "f"(v[q].x), "f"(v[q].y), "f"(v[q].z), "f"(v[q].w)
                         : "memory");
        }
    }
    if (lane < cnt) {
        atomicAdd(g_cnt_e + e[lane], 1.0f);
        atomicAdd(g_cnt_n + n[lane], 1.0f);
    }
}

// ---- scatter2: e2[edge] -> out[node], 4 incidences per warp ----
__global__ void scatter2_kernel(const int* __restrict__ nidx,
                                const int* __restrict__ eidx,
                                float* __restrict__ out, int ninc) {
    int gw = (blockIdx.x * blockDim.x + threadIdx.x) >> 5;
    int lane = threadIdx.x & 31;
    int base = gw * 4;
    if (base >= ninc) return;
    int cnt = min(4, ninc - base);

    int n[4], e[4];
#pragma unroll
    for (int q = 0; q < 4; q++) {
        int i = (q < cnt) ? base + q : base;
        n[q] = __ldg(nidx + i);
        e[q] = __ldg(eidx + i);
    }
    float4 v[4];
#pragma unroll
    for (int q = 0; q < 4; q++)
        v[q] = *reinterpret_cast<const float4*>(g_e2 + (size_t)e[q] * CC + lane * 4);
#pragma unroll
    for (int q = 0; q < 4; q++) {
        if (q < cnt) {
            float* dst = out + (size_t)n[q] * CC + lane * 4;
            asm volatile("red.global.add.v4.f32 [%0], {%1,%2,%3,%4};"
                         :: "l"(dst), "f"(v[q].x), "f"(v[q].y), "f"(v[q].z), "f"(v[q].w)
                         : "memory");
        }
    }
}

__device__ __forceinline__ uint32_t f2tf32(float f) {
    uint32_t u;
    asm("cvt.rna.tf32.f32 %0, %1;" : "=r"(u) : "f"(f));
    return u;
}

// ---- fused double tf32 GEMM per 64-row tile ----
// Stage A: T = relu( (esum/cnt) @ W1^T + b1 )   [64 x 128], kept in smem (tf32)
// Stage B: e2 = T @ W2^T + b2                   [64 x 128], written to gmem
__global__ void __launch_bounds__(256) fused_gemm(const float* __restrict__ W1,
                                                  const float* __restrict__ b1,
                                                  const float* __restrict__ W2,
                                                  const float* __restrict__ b2) {
    extern __shared__ uint32_t smem[];
    uint32_t (*Ts)[132] = reinterpret_cast<uint32_t(*)[132]>(smem);            // 64x132
    uint32_t (*Bs)[36]  = reinterpret_cast<uint32_t(*)[36]>(smem + 64 * 132);  // 128x36
    uint32_t (*As)[36]  = reinterpret_cast<uint32_t(*)[36]>(smem + 64 * 132 + 128 * 36); // 64x36

    const int M = NE;
    const int tid = threadIdx.x;
    const int lane = tid & 31;
    const int g = lane >> 2;
    const int tig = lane & 3;
    const int w = tid >> 5;
    const int wm = w >> 2;
    const int wn = w & 3;
    const int row0 = blockIdx.x * 64;

    const int a_row = tid >> 3;
    const int a_c4  = tid & 7;
    const int b_row = tid >> 1;
    const int b_c4  = (tid & 1) * 4;

    float ascale[2] = {1.f, 1.f};
#pragma unroll
    for (int p = 0; p < 2; p++) {
        int gm = row0 + a_row + p * 32;
        if (gm < M) ascale[p] = 1.f / fmaxf(__ldg(g_cnt_e + gm), 1.f);
    }

    float c[2][4][4];
#pragma unroll
    for (int mt = 0; mt < 2; mt++)
#pragma unroll
        for (int nt = 0; nt < 4; nt++)
#pragma unroll
            for (int r = 0; r < 4; r++) c[mt][nt][r] = 0.f;

    // ================= Stage A =================
#pragma unroll
    for (int ch = 0; ch < 4; ch++) {
        const int kb = ch * 32;
        float4 ra[2], rb[4];
#pragma unroll
        for (int p = 0; p < 2; p++) {
            int gm = row0 + a_row + p * 32;
            float4 v = make_float4(0.f, 0.f, 0.f, 0.f);
            if (gm < M)
                v = *reinterpret_cast<const float4*>(g_esum + (size_t)gm * CC + kb + a_c4 * 4);
            v.x *= ascale[p]; v.y *= ascale[p]; v.z *= ascale[p]; v.w *= ascale[p];
            ra[p] = v;
        }
#pragma unroll
        for (int p = 0; p < 4; p++)
            rb[p] = *reinterpret_cast<const float4*>(W1 + (size_t)b_row * CC + kb + (b_c4 + p) * 4);
        if (ch > 0) __syncthreads();
#pragma unroll
        for (int p = 0; p < 2; p++) {
            int r = a_row + p * 32;
            As[r][a_c4 * 4 + 0] = f2tf32(ra[p].x);
            As[r][a_c4 * 4 + 1] = f2tf32(ra[p].y);
            As[r][a_c4 * 4 + 2] = f2tf32(ra[p].z);
            As[r][a_c4 * 4 + 3] = f2tf32(ra[p].w);
        }
#pragma unroll
        for (int p = 0; p < 4; p++) {
            int kcol = (b_c4 + p) * 4;
            Bs[b_row][kcol + 0] = f2tf32(rb[p].x);
            Bs[b_row][kcol + 1] = f2tf32(rb[p].y);
            Bs[b_row][kcol + 2] = f2tf32(rb[p].z);
            Bs[b_row][kcol + 3] = f2tf32(rb[p].w);
        }
        __syncthreads();
#pragma unroll
        for (int ks = 0; ks < 4; ks++) {
            const int k0 = ks * 8;
            uint32_t a[2][4], b[4][2];
#pragma unroll
            for (int mt = 0; mt < 2; mt++) {
                int mb = wm * 32 + mt * 16;
                a[mt][0] = As[mb + g][k0 + tig];
                a[mt][1] = As[mb + g + 8][k0 + tig];
                a[mt][2] = As[mb + g][k0 + tig + 4];
                a[mt][3] = As[mb + g + 8][k0 + tig + 4];
            }
#pragma unroll
            for (int nt = 0; nt < 4; nt++) {
                int nb = wn * 32 + nt * 8;
                b[nt][0] = Bs[nb + g][k0 + tig];
                b[nt][1] = Bs[nb + g][k0 + tig + 4];
            }
#pragma unroll
            for (int mt = 0; mt < 2; mt++)
#pragma unroll
                for (int nt = 0; nt < 4; nt++)
                    asm volatile(
                        "mma.sync.aligned.m16n8k8.row.col.f32.tf32.tf32.f32 "
                        "{%0,%1,%2,%3}, {%4,%5,%6,%7}, {%8,%9}, {%0,%1,%2,%3};"
                        : "+f"(c[mt][nt][0]), "+f"(c[mt][nt][1]),
                          "+f"(c[mt][nt][2]), "+f"(c[mt][nt][3])
                        : "r"(a[mt][0]), "r"(a[mt][1]), "r"(a[mt][2]), "r"(a[mt][3]),
                          "r"(b[nt][0]), "r"(b[nt][1]));
        }
    }
    __syncthreads();

    // ---- write T = relu(c + b1) into Ts (tf32), reset accumulators ----
#pragma unroll
    for (int nt = 0; nt < 4; nt++) {
        int col = wn * 32 + nt * 8 + tig * 2;
        float bb0 = __ldg(b1 + col);
        float bb1 = __ldg(b1 + col + 1);
#pragma unroll
        for (int mt = 0; mt < 2; mt++) {
            int mb = wm * 32 + mt * 16;
            Ts[mb + g][col]         = f2tf32(fmaxf(c[mt][nt][0] + bb0, 0.f));
            Ts[mb + g][col + 1]     = f2tf32(fmaxf(c[mt][nt][1] + bb1, 0.f));
            Ts[mb + g + 8][col]     = f2tf32(fmaxf(c[mt][nt][2] + bb0, 0.f));
            Ts[mb + g + 8][col + 1] = f2tf32(fmaxf(c[mt][nt][3] + bb1, 0.f));
            c[mt][nt][0] = 0.f; c[mt][nt][1] = 0.f;
            c[mt][nt][2] = 0.f; c[mt][nt][3] = 0.f;
        }
    }

    // ================= Stage B =================
#pragma unroll
    for (int ch = 0; ch < 4; ch++) {
        const int kb = ch * 32;
        float4 rb[4];
#pragma unroll
        for (int p = 0; p < 4; p++)
            rb[p] = *reinterpret_cast<const float4*>(W2 + (size_t)b_row * CC + kb + (b_c4 + p) * 4);
        __syncthreads();
#pragma unroll
        for (int p = 0; p < 4; p++) {
            int kcol = (b_c4 + p) * 4;
            Bs[b_row][kcol + 0] = f2tf32(rb[p].x);
            Bs[b_row][kcol + 1] = f2tf32(rb[p].y);
            Bs[b_row][kcol + 2] = f2tf32(rb[p].z);
            Bs[b_row][kcol + 3] = f2tf32(rb[p].w);
        }
        __syncthreads();
#pragma unroll
        for (int ks = 0; ks < 4; ks++) {
            const int k0 = ks * 8;
            const int kk = kb + k0;
            uint32_t a[2][4], b[4][2];
#pragma unroll
            for (int mt = 0; mt < 2; mt++) {
                int mb = wm * 32 + mt * 16;
                a[mt][0] = Ts[mb + g][kk + tig];
                a[mt][1] = Ts[mb + g + 8][kk + tig];
                a[mt][2] = Ts[mb + g][kk + tig + 4];
                a[mt][3] = Ts[mb + g + 8][kk + tig + 4];
            }
#pragma unroll
            for (int nt = 0; nt < 4; nt++) {
                int nb = wn * 32 + nt * 8;
                b[nt][0] = Bs[nb + g][k0 + tig];
                b[nt][1] = Bs[nb + g][k0 + tig + 4];
            }
#pragma unroll
            for (int mt = 0; mt < 2; mt++)
#pragma unroll
                for (int nt = 0; nt < 4; nt++)
                    asm volatile(
                        "mma.sync.aligned.m16n8k8.row.col.f32.tf32.tf32.f32 "
                        "{%0,%1,%2,%3}, {%4,%5,%6,%7}, {%8,%9}, {%0,%1,%2,%3};"
                        : "+f"(c[mt][nt][0]), "+f"(c[mt][nt][1]),
                          "+f"(c[mt][nt][2]), "+f"(c[mt][nt][3])
                        : "r"(a[mt][0]), "r"(a[mt][1]), "r"(a[mt][2]), "r"(a[mt][3]),
                          "r"(b[nt][0]), "r"(b[nt][1]));
        }
    }

    // ---- epilogue: e2 = c + b2 ----
#pragma unroll
    for (int nt = 0; nt < 4; nt++) {
        int col = wn * 32 + nt * 8 + tig * 2;
        float bb0 = __ldg(b2 + col);
        float bb1 = __ldg(b2 + col + 1);
#pragma unroll
        for (int mt = 0; mt < 2; mt++) {
            int mb = row0 + wm * 32 + mt * 16;
            int r0 = mb + g;
            int r1 = mb + g + 8;
            if (r0 < M)
                *reinterpret_cast<float2*>(g_e2 + (size_t)r0 * CC + col) =
                    make_float2(c[mt][nt][0] + bb0, c[mt][nt][1] + bb1);
            if (r1 < M)
                *reinterpret_cast<float2*>(g_e2 + (size_t)r1 * CC + col) =
                    make_float2(c[mt][nt][2] + bb0, c[mt][nt][3] + bb1);
        }
    }
}

// ---- finalize: out = relu(out / max(cnt_n, 1)) ----
__global__ void finalize_kernel(float* __restrict__ out) {
    int i = blockIdx.x * blockDim.x + threadIdx.x;
    int stride = gridDim.x * blockDim.x;
    float4* p = reinterpret_cast<float4*>(out);
    for (; i < NN * CC / 4; i += stride) {
        int m = i >> 5;
        float s = 1.f / fmaxf(g_cnt_n[m], 1.f);
        float4 v = p[i];
        v.x = fmaxf(v.x * s, 0.f);
        v.y = fmaxf(v.y * s, 0.f);
        v.z = fmaxf(v.z * s, 0.f);
        v.w = fmaxf(v.w * s, 0.f);
        p[i] = v;
    }
}

extern "C" void kernel_launch(void* const* d_in, const int* in_sizes, int n_in,
                              void* d_out, int out_size) {
    const float* x  = (const float*)d_in[0];
    const int*   hi = (const int*)d_in[1];
    const float* W1 = (const float*)d_in[2];
    const float* b1 = (const float*)d_in[3];
    const float* W2 = (const float*)d_in[4];
    const float* b2 = (const float*)d_in[5];
    float* out = (float*)d_out;

    int ninc = in_sizes[1] / 2;
    const int* nidx = hi;          // hyperedge_index[0]
    const int* eidx = hi + ninc;   // hyperedge_index[1]

    constexpr int SMEM_BYTES = (64 * 132 + 128 * 36 + 64 * 36) * 4;  // 61440
    static int attr_set = 0;
    if (!attr_set) {
        cudaFuncSetAttribute(fused_gemm, cudaFuncAttributeMaxDynamicSharedMemorySize,
                             SMEM_BYTES);
        attr_set = 1;
    }

    // 8 warps/block, 4 incidences/warp -> 32 incidences per block
    int sc_blocks = (ninc + 31) / 32;
    prep_kernel<<<1024, 256>>>(out);
    scatter1_kernel<<<sc_blocks, 256>>>(x, nidx, eidx, ninc);
    fused_gemm<<<(NE + 63) / 64, 256, SMEM_BYTES>>>(W1, b1, W2, b2);
    scatter2_kernel<<<sc_blocks, 256>>>(nidx, eidx, out, ninc);
    finalize_kernel<<<1024, 256>>>(out);
}

// round 13
// speedup vs baseline: 2.6485x; 1.5041x over previous
#include <cuda_runtime.h>
#include <cstdint>

#define NN 50000
#define NE 25000
#define CC 128
#define MAXINC 700000

// ---- scratch (device globals; no allocation) ----
__device__ __align__(16) float g_emean[NE * CC];  // per-edge mean of gathered x
__device__ __align__(16) float g_e2[NE * CC];     // (relu(mean@W1^T+b1))@W2^T + b2
__device__ int g_cc_e[NE];      // per-edge degree
__device__ int g_cc_n[NN];      // per-node degree
__device__ int g_off_e[NE];     // region start offsets
__device__ int g_off_n[NN];
__device__ int g_pos_e[NE];     // fill cursors
__device__ int g_pos_n[NN];
__device__ int g_cur_e;         // global cursors for offset assignment
__device__ int g_cur_n;
__device__ int g_lst_e[MAXINC]; // node ids grouped by edge
__device__ int g_lst_n[MAXINC]; // edge ids grouped by node

// ---- prep: zero degree counters + cursors ----
__global__ void prep_kernel() {
    int tid = blockIdx.x * blockDim.x + threadIdx.x;
    int stride = gridDim.x * blockDim.x;
    for (int i = tid; i < NE; i += stride) g_cc_e[i] = 0;
    for (int i = tid; i < NN; i += stride) g_cc_n[i] = 0;
    if (tid == 0) { g_cur_e = 0; g_cur_n = 0; }
}

// ---- count: 4 incidences per thread ----
__global__ void count_kernel(const int* __restrict__ nidx,
                             const int* __restrict__ eidx, int ninc) {
    int base = (blockIdx.x * blockDim.x + threadIdx.x) * 4;
    if (base >= ninc) return;
    int cnt = min(4, ninc - base);
#pragma unroll
    for (int q = 0; q < 4; q++) {
        if (q < cnt) {
            atomicAdd(&g_cc_e[__ldg(eidx + base + q)], 1);
            atomicAdd(&g_cc_n[__ldg(nidx + base + q)], 1);
        }
    }
}

// ---- offsets: block-aggregated atomic-cursor assignment ----
// blocks [0, EB) -> edges, blocks [EB, EB+NB) -> nodes. 1024 threads/block.
#define EB ((NE + 1023) / 1024)
#define NB ((NN + 1023) / 1024)
__global__ void __launch_bounds__(1024) offset_kernel() {
    bool is_node = blockIdx.x >= EB;
    const int* cc = is_node ? g_cc_n : g_cc_e;
    int* off = is_node ? g_off_n : g_off_e;
    int* pos = is_node ? g_pos_n : g_pos_e;
    int* cur = is_node ? &g_cur_n : &g_cur_e;
    int n = is_node ? NN : NE;
    int blk = is_node ? (blockIdx.x - EB) : blockIdx.x;

    __shared__ int warp_sums[32];
    __shared__ int s_base;
    int tid = threadIdx.x, lane = tid & 31, wid = tid >> 5;
    int i = blk * 1024 + tid;
    int v = (i < n) ? cc[i] : 0;
    int s = v;
#pragma unroll
    for (int d = 1; d < 32; d <<= 1) {
        int t = __shfl_up_sync(0xffffffffu, s, d);
        if (lane >= d) s += t;
    }
    if (lane == 31) warp_sums[wid] = s;
    __syncthreads();
    if (wid == 0) {
        int ws = warp_sums[lane];
#pragma unroll
        for (int d = 1; d < 32; d <<= 1) {
            int t = __shfl_up_sync(0xffffffffu, ws, d);
            if (lane >= d) ws += t;
        }
        warp_sums[lane] = ws;
        if (lane == 31) s_base = atomicAdd(cur, ws);
    }
    __syncthreads();
    int excl = s - v + (wid ? warp_sums[wid - 1] : 0) + s_base;
    if (i < n) { off[i] = excl; pos[i] = excl; }
}

// ---- fill: 4 incidences per thread, independent atomic chains ----
__global__ void fill_kernel(const int* __restrict__ nidx,
                            const int* __restrict__ eidx, int ninc) {
    int base = (blockIdx.x * blockDim.x + threadIdx.x) * 4;
    if (base >= ninc) return;
    int cnt = min(4, ninc - base);
    int n[4], e[4];
#pragma unroll
    for (int q = 0; q < 4; q++) {
        int i = (q < cnt) ? base + q : base;
        n[q] = __ldg(nidx + i);
        e[q] = __ldg(eidx + i);
    }
    int p[4], r[4];
#pragma unroll
    for (int q = 0; q < 4; q++) {
        if (q < cnt) {
            p[q] = atomicAdd(&g_pos_e[e[q]], 1);
            r[q] = atomicAdd(&g_pos_n[n[q]], 1);
        }
    }
#pragma unroll
    for (int q = 0; q < 4; q++) {
        if (q < cnt) {
            g_lst_e[p[q]] = n[q];
            g_lst_n[r[q]] = e[q];
        }
    }
}

// ---- gather1: g_emean[e] = mean of x[n] over incident nodes ----
__global__ void gather1_kernel(const float* __restrict__ x) {
    int gw = (blockIdx.x * blockDim.x + threadIdx.x) >> 5;
    int lane = threadIdx.x & 31;
    if (gw >= NE) return;
    int off = __ldg(g_off_e + gw);
    int deg = __ldg(g_cc_e + gw);
    float4 acc = make_float4(0.f, 0.f, 0.f, 0.f);
    int j = 0;
    for (; j + 4 <= deg; j += 4) {
        int n0 = __ldg(g_lst_e + off + j);
        int n1 = __ldg(g_lst_e + off + j + 1);
        int n2 = __ldg(g_lst_e + off + j + 2);
        int n3 = __ldg(g_lst_e + off + j + 3);
        float4 v0 = *reinterpret_cast<const float4*>(x + (size_t)n0 * CC + lane * 4);
        float4 v1 = *reinterpret_cast<const float4*>(x + (size_t)n1 * CC + lane * 4);
        float4 v2 = *reinterpret_cast<const float4*>(x + (size_t)n2 * CC + lane * 4);
        float4 v3 = *reinterpret_cast<const float4*>(x + (size_t)n3 * CC + lane * 4);
        acc.x += v0.x + v1.x + v2.x + v3.x;
        acc.y += v0.y + v1.y + v2.y + v3.y;
        acc.z += v0.z + v1.z + v2.z + v3.z;
        acc.w += v0.w + v1.w + v2.w + v3.w;
    }
    for (; j < deg; j++) {
        int n0 = __ldg(g_lst_e + off + j);
        float4 v0 = *reinterpret_cast<const float4*>(x + (size_t)n0 * CC + lane * 4);
        acc.x += v0.x; acc.y += v0.y; acc.z += v0.z; acc.w += v0.w;
    }
    float s = 1.f / (float)max(deg, 1);
    acc.x *= s; acc.y *= s; acc.z *= s; acc.w *= s;
    *reinterpret_cast<float4*>(g_emean + (size_t)gw * CC + lane * 4) = acc;
}

// ---- gather2: out[n] = relu(mean of g_e2[e] over incident edges) ----
__global__ void gather2_kernel(float* __restrict__ out) {
    int gw = (blockIdx.x * blockDim.x + threadIdx.x) >> 5;
    int lane = threadIdx.x & 31;
    if (gw >= NN) return;
    int off = __ldg(g_off_n + gw);
    int deg = __ldg(g_cc_n + gw);
    float4 acc = make_float4(0.f, 0.f, 0.f, 0.f);
    int j = 0;
    for (; j + 4 <= deg; j += 4) {
        int e0 = __ldg(g_lst_n + off + j);
        int e1 = __ldg(g_lst_n + off + j + 1);
        int e2i = __ldg(g_lst_n + off + j + 2);
        int e3 = __ldg(g_lst_n + off + j + 3);
        float4 v0 = *reinterpret_cast<const float4*>(g_e2 + (size_t)e0 * CC + lane * 4);
        float4 v1 = *reinterpret_cast<const float4*>(g_e2 + (size_t)e1 * CC + lane * 4);
        float4 v2 = *reinterpret_cast<const float4*>(g_e2 + (size_t)e2i * CC + lane * 4);
        float4 v3 = *reinterpret_cast<const float4*>(g_e2 + (size_t)e3 * CC + lane * 4);
        acc.x += v0.x + v1.x + v2.x + v3.x;
        acc.y += v0.y + v1.y + v2.y + v3.y;
        acc.z += v0.z + v1.z + v2.z + v3.z;
        acc.w += v0.w + v1.w + v2.w + v3.w;
    }
    for (; j < deg; j++) {
        int e0 = __ldg(g_lst_n + off + j);
        float4 v0 = *reinterpret_cast<const float4*>(g_e2 + (size_t)e0 * CC + lane * 4);
        acc.x += v0.x; acc.y += v0.y; acc.z += v0.z; acc.w += v0.w;
    }
    float s = 1.f / (float)max(deg, 1);
    acc.x = fmaxf(acc.x * s, 0.f);
    acc.y = fmaxf(acc.y * s, 0.f);
    acc.z = fmaxf(acc.z * s, 0.f);
    acc.w = fmaxf(acc.w * s, 0.f);
    *reinterpret_cast<float4*>(out + (size_t)gw * CC + lane * 4) = acc;
}

__device__ __forceinline__ uint32_t f2tf32(float f) {
    uint32_t u;
    asm("cvt.rna.tf32.f32 %0, %1;" : "=r"(u) : "f"(f));
    return u;
}

// ---- fused double tf32 GEMM per 64-row tile ----
// Stage A: T = relu( g_emean @ W1^T + b1 )  [64x128], kept in smem (tf32)
// Stage B: e2 = T @ W2^T + b2               [64x128], written to gmem
__global__ void __launch_bounds__(256) fused_gemm(const float* __restrict__ W1,
                                                  const float* __restrict__ b1,
                                                  const float* __restrict__ W2,
                                                  const float* __restrict__ b2) {
    extern __shared__ uint32_t smem[];
    uint32_t (*Ts)[132] = reinterpret_cast<uint32_t(*)[132]>(smem);
    uint32_t (*Bs)[36]  = reinterpret_cast<uint32_t(*)[36]>(smem + 64 * 132);
    uint32_t (*As)[36]  = reinterpret_cast<uint32_t(*)[36]>(smem + 64 * 132 + 128 * 36);

    const int M = NE;
    const int tid = threadIdx.x;
    const int lane = tid & 31;
    const int g = lane >> 2;
    const int tig = lane & 3;
    const int w = tid >> 5;
    const int wm = w >> 2;
    const int wn = w & 3;
    const int row0 = blockIdx.x * 64;

    const int a_row = tid >> 3;
    const int a_c4  = tid & 7;
    const int b_row = tid >> 1;
    const int b_c4  = (tid & 1) * 4;

    float c[2][4][4];
#pragma unroll
    for (int mt = 0; mt < 2; mt++)
#pragma unroll
        for (int nt = 0; nt < 4; nt++)
#pragma unroll
            for (int r = 0; r < 4; r++) c[mt][nt][r] = 0.f;

    // ================= Stage A =================
#pragma unroll
    for (int ch = 0; ch < 4; ch++) {
        const int kb = ch * 32;
        float4 ra[2], rb[4];
#pragma unroll
        for (int p = 0; p < 2; p++) {
            int gm = row0 + a_row + p * 32;
            float4 v = make_float4(0.f, 0.f, 0.f, 0.f);
            if (gm < M)
                v = *reinterpret_cast<const float4*>(g_emean + (size_t)gm * CC + kb + a_c4 * 4);
            ra[p] = v;
        }
#pragma unroll
        for (int p = 0; p < 4; p++)
            rb[p] = *reinterpret_cast<const float4*>(W1 + (size_t)b_row * CC + kb + (b_c4 + p) * 4);
        if (ch > 0) __syncthreads();
#pragma unroll
        for (int p = 0; p < 2; p++) {
            int r = a_row + p * 32;
            As[r][a_c4 * 4 + 0] = f2tf32(ra[p].x);
            As[r][a_c4 * 4 + 1] = f2tf32(ra[p].y);
            As[r][a_c4 * 4 + 2] = f2tf32(ra[p].z);
            As[r][a_c4 * 4 + 3] = f2tf32(ra[p].w);
        }
#pragma unroll
        for (int p = 0; p < 4; p++) {
            int kcol = (b_c4 + p) * 4;
            Bs[b_row][kcol + 0] = f2tf32(rb[p].x);
            Bs[b_row][kcol + 1] = f2tf32(rb[p].y);
            Bs[b_row][kcol + 2] = f2tf32(rb[p].z);
            Bs[b_row][kcol + 3] = f2tf32(rb[p].w);
        }
        __syncthreads();
#pragma unroll
        for (int ks = 0; ks < 4; ks++) {
            const int k0 = ks * 8;
            uint32_t a[2][4], b[4][2];
#pragma unroll
            for (int mt = 0; mt < 2; mt++) {
                int mb = wm * 32 + mt * 16;
                a[mt][0] = As[mb + g][k0 + tig];
                a[mt][1] = As[mb + g + 8][k0 + tig];
                a[mt][2] = As[mb + g][k0 + tig + 4];
                a[mt][3] = As[mb + g + 8][k0 + tig + 4];
            }
#pragma unroll
            for (int nt = 0; nt < 4; nt++) {
                int nb = wn * 32 + nt * 8;
                b[nt][0] = Bs[nb + g][k0 + tig];
                b[nt][1] = Bs[nb + g][k0 + tig + 4];
            }
#pragma unroll
            for (int mt = 0; mt < 2; mt++)
#pragma unroll
                for (int nt = 0; nt < 4; nt++)
                    asm volatile(
                        "mma.sync.aligned.m16n8k8.row.col.f32.tf32.tf32.f32 "
                        "{%0,%1,%2,%3}, {%4,%5,%6,%7}, {%8,%9}, {%0,%1,%2,%3};"
                        : "+f"(c[mt][nt][0]), "+f"(c[mt][nt][1]),
                          "+f"(c[mt][nt][2]), "+f"(c[mt][nt][3])
                        : "r"(a[mt][0]), "r"(a[mt][1]), "r"(a[mt][2]), "r"(a[mt][3]),
                          "r"(b[nt][0]), "r"(b[nt][1]));
        }
    }
    __syncthreads();

    // ---- T = relu(c + b1) -> Ts (tf32); reset accumulators ----
#pragma unroll
    for (int nt = 0; nt < 4; nt++) {
        int col = wn * 32 + nt * 8 + tig * 2;
        float bb0 = __ldg(b1 + col);
        float bb1 = __ldg(b1 + col + 1);
#pragma unroll
        for (int mt = 0; mt < 2; mt++) {
            int mb = wm * 32 + mt * 16;
            Ts[mb + g][col]         = f2tf32(fmaxf(c[mt][nt][0] + bb0, 0.f));
            Ts[mb + g][col + 1]     = f2tf32(fmaxf(c[mt][nt][1] + bb1, 0.f));
            Ts[mb + g + 8][col]     = f2tf32(fmaxf(c[mt][nt][2] + bb0, 0.f));
            Ts[mb + g + 8][col + 1] = f2tf32(fmaxf(c[mt][nt][3] + bb1, 0.f));
            c[mt][nt][0] = 0.f; c[mt][nt][1] = 0.f;
            c[mt][nt][2] = 0.f; c[mt][nt][3] = 0.f;
        }
    }

    // ================= Stage B =================
#pragma unroll
    for (int ch = 0; ch < 4; ch++) {
        const int kb = ch * 32;
        float4 rb[4];
#pragma unroll
        for (int p = 0; p < 4; p++)
            rb[p] = *reinterpret_cast<const float4*>(W2 + (size_t)b_row * CC + kb + (b_c4 + p) * 4);
        __syncthreads();
#pragma unroll
        for (int p = 0; p < 4; p++) {
            int kcol = (b_c4 + p) * 4;
            Bs[b_row][kcol + 0] = f2tf32(rb[p].x);
            Bs[b_row][kcol + 1] = f2tf32(rb[p].y);
            Bs[b_row][kcol + 2] = f2tf32(rb[p].z);
            Bs[b_row][kcol + 3] = f2tf32(rb[p].w);
        }
        __syncthreads();
#pragma unroll
        for (int ks = 0; ks < 4; ks++) {
            const int k0 = ks * 8;
            const int kk = kb + k0;
            uint32_t a[2][4], b[4][2];
#pragma unroll
            for (int mt = 0; mt < 2; mt++) {
                int mb = wm * 32 + mt * 16;
                a[mt][0] = Ts[mb + g][kk + tig];
                a[mt][1] = Ts[mb + g + 8][kk + tig];
                a[mt][2] = Ts[mb + g][kk + tig + 4];
                a[mt][3] = Ts[mb + g + 8][kk + tig + 4];
            }
#pragma unroll
            for (int nt = 0; nt < 4; nt++) {
                int nb = wn * 32 + nt * 8;
                b[nt][0] = Bs[nb + g][k0 + tig];
                b[nt][1] = Bs[nb + g][k0 + tig + 4];
            }
#pragma unroll
            for (int mt = 0; mt < 2; mt++)
#pragma unroll
                for (int nt = 0; nt < 4; nt++)
                    asm volatile(
                        "mma.sync.aligned.m16n8k8.row.col.f32.tf32.tf32.f32 "
                        "{%0,%1,%2,%3}, {%4,%5,%6,%7}, {%8,%9}, {%0,%1,%2,%3};"
                        : "+f"(c[mt][nt][0]), "+f"(c[mt][nt][1]),
                          "+f"(c[mt][nt][2]), "+f"(c[mt][nt][3])
                        : "r"(a[mt][0]), "r"(a[mt][1]), "r"(a[mt][2]), "r"(a[mt][3]),
                          "r"(b[nt][0]), "r"(b[nt][1]));
        }
    }

    // ---- epilogue: e2 = c + b2 ----
#pragma unroll
    for (int nt = 0; nt < 4; nt++) {
        int col = wn * 32 + nt * 8 + tig * 2;
        float bb0 = __ldg(b2 + col);
        float bb1 = __ldg(b2 + col + 1);
#pragma unroll
        for (int mt = 0; mt < 2; mt++) {
            int mb = row0 + wm * 32 + mt * 16;
            int r0 = mb + g;
            int r1 = mb + g + 8;
            if (r0 < M)
                *reinterpret_cast<float2*>(g_e2 + (size_t)r0 * CC + col) =
                    make_float2(c[mt][nt][0] + bb0, c[mt][nt][1] + bb1);
            if (r1 < M)
                *reinterpret_cast<float2*>(g_e2 + (size_t)r1 * CC + col) =
                    make_float2(c[mt][nt][2] + bb0, c[mt][nt][3] + bb1);
        }
    }
}

extern "C" void kernel_launch(void* const* d_in, const int* in_sizes, int n_in,
                              void* d_out, int out_size) {
    const float* x  = (const float*)d_in[0];
    const int*   hi = (const int*)d_in[1];
    const float* W1 = (const float*)d_in[2];
    const float* b1 = (const float*)d_in[3];
    const float* W2 = (const float*)d_in[4];
    const float* b2 = (const float*)d_in[5];
    float* out = (float*)d_out;

    int ninc = in_sizes[1] / 2;
    const int* nidx = hi;          // hyperedge_index[0]
    const int* eidx = hi + ninc;   // hyperedge_index[1]

    constexpr int SMEM_BYTES = (64 * 132 + 128 * 36 + 64 * 36) * 4;  // 61440
    static int attr_set = 0;
    if (!attr_set) {
        cudaFuncSetAttribute(fused_gemm, cudaFuncAttributeMaxDynamicSharedMemorySize,
                             SMEM_BYTES);
        attr_set = 1;
    }

    int qthreads = (ninc + 3) / 4;
    prep_kernel<<<512, 256>>>();
    count_kernel<<<(qthreads + 255) / 256, 256>>>(nidx, eidx, ninc);
    offset_kernel<<<EB + NB, 1024>>>();
    fill_kernel<<<(qthreads + 255) / 256, 256>>>(nidx, eidx, ninc);
    gather1_kernel<<<(NE * 32 + 255) / 256, 256>>>(x);
    fused_gemm<<<(NE + 63) / 64, 256, SMEM_BYTES>>>(W1, b1, W2, b2);
    gather2_kernel<<<(NN * 32 + 255) / 256, 256>>>(out);
}